// round 12
// baseline (speedup 1.0000x reference)
#include <cuda_runtime.h>
#include <math.h>
#include <stdint.h>

#define FF  128     // frames
#define NP  300     // predictions per frame
#define MT  32      // targets per frame
#define KID 512     // id classes
#define NTH 320     // threads per block (10 warps)

__device__ double g_part[FF * 3];   // per-frame partials: l1, giou, nll
__device__ int    g_done = 0;       // completion counter (self-resetting)

// order-preserving map float -> uint32 (total order, equality preserved)
__device__ __forceinline__ unsigned enc_f(float d) {
    int u = __float_as_int(d);
    return (unsigned)(u ^ ((u >> 31) | 0x80000000));
}
__device__ __forceinline__ float dec_f(unsigned e) {
    int u = (e & 0x80000000u) ? (int)(e ^ 0x80000000u) : ~(int)e;
    return __int_as_float(u);
}

// ============================================================
// Fused kernel, one block (320 threads) per frame:
// cost (shared, f32, exact IEEE division) -> row reduction +
// greedy pass 1 (R8 solver, proven bit-exact) -> speculative
// L2 prefetch of matched id-logit rows -> Dijkstra for
// contested rows -> software-pipelined loss partials ->
// last-block final reduction.
// ============================================================
__global__ void __launch_bounds__(NTH, 1)
fused_kernel(const float* __restrict__ pl,
             const float* __restrict__ pb,
             const float* __restrict__ il,
             const int*   __restrict__ labels,
             const float* __restrict__ tbx,
             const int*   __restrict__ tids,
             float* __restrict__ out) {
    __shared__ float  s_cost[MT * NP];      // 38400 B [m][n]
    __shared__ float  s_u[MT + 2];
    __shared__ short  s_p[NP + 1];
    __shared__ short  s_way[NP + 1];
    __shared__ short  s_rowarg[MT];         // 1-based greedy argmin col per row
    __shared__ unsigned s_amask;            // greedy-assigned rows bitmask
    __shared__ unsigned s_wenc[2][10];
    __shared__ int      s_widx[2][10];
    __shared__ int    s_pidx[MT];
    __shared__ float  s_tb[MT][4];
    __shared__ int    s_lab[MT];
    __shared__ float  s_l1[MT], s_g[MT], s_nll[MT];
    __shared__ int    s_last;
    __shared__ double sa[4], sb[4], sc[4];

    const int f    = blockIdx.x;
    const int tid  = threadIdx.x;
    const int lane = tid & 31;
    const int wrp  = tid >> 5;
    const unsigned FULL = 0xFFFFFFFFu;

    // ---- stage targets + init ----
    if (tid < MT) {
        s_lab[tid] = labels[f * MT + tid];
        #pragma unroll
        for (int c = 0; c < 4; ++c) s_tb[tid][c] = tbx[(f * MT + tid) * 4 + c];
    }
    if (tid < MT + 2) s_u[tid] = 0.0f;
    if (tid <= NP) s_p[tid] = 0;
    __syncthreads();

    // ---- phase 1: cost matrix (column n = tid, loop over m), exact division ----
    if (tid < NP) {
        const int n = tid;
        float2 lg = ((const float2*)pl)[f * NP + n];
        float mx = fmaxf(lg.x, lg.y);
        float e0 = __expf(lg.x - mx), e1 = __expf(lg.y - mx);
        float inv = 1.0f / (e0 + e1);
        float p0 = e0 * inv, p1 = e1 * inv;
        float4 box = ((const float4*)pb)[f * NP + n];
        float cx = box.x, cy = box.y, w = box.z, h = box.w;
        float ax0 = cx - 0.5f * w, ay0 = cy - 0.5f * h;
        float ax1 = cx + 0.5f * w, ay1 = cy + 0.5f * h;
        float area1 = (ax1 - ax0) * (ay1 - ay0);
        #pragma unroll 4
        for (int m = 0; m < MT; ++m) {
            float bcx = s_tb[m][0], bcy = s_tb[m][1], bw = s_tb[m][2], bh = s_tb[m][3];
            float bx0 = bcx - 0.5f * bw, by0 = bcy - 0.5f * bh;
            float bx1 = bcx + 0.5f * bw, by1 = bcy + 0.5f * bh;
            float area2 = (bx1 - bx0) * (by1 - by0);
            float iw = fmaxf(fminf(ax1, bx1) - fmaxf(ax0, bx0), 0.0f);
            float ih = fmaxf(fminf(ay1, by1) - fmaxf(ay0, by0), 0.0f);
            float inter = iw * ih;
            float uni = area1 + area2 - inter;
            float iou = inter / uni;
            float cw = fmaxf(fmaxf(ax1, bx1) - fminf(ax0, bx0), 0.0f);
            float ch = fmaxf(fmaxf(ay1, by1) - fminf(ay0, by0), 0.0f);
            float ac = cw * ch;
            float giou = iou - (ac - uni) / ac;
            float l1c = fabsf(cx - bcx) + fabsf(cy - bcy) + fabsf(w - bw) + fabsf(h - bh);
            float prob = (s_lab[m] == 0) ? p0 : p1;
            s_cost[m * NP + n] = -2.0f * prob + 5.0f * l1c - 2.0f * giou;
        }
    }
    __syncthreads();

    // ---- phase 2a: row reduction + greedy assignment (R8, proven) ----
    {
        const unsigned long long UMAX = 0xFFFFFFFFFFFFFFFFULL;
        for (int r = wrp; r < MT; r += 10) {
            const float* crow = s_cost + r * NP;
            unsigned long long best = UMAX;
            for (int j = lane; j < NP; j += 32) {
                unsigned long long key =
                    ((unsigned long long)enc_f(crow[j]) << 9) | (unsigned)(j + 1);
                if (key < best) best = key;
            }
            #pragma unroll
            for (int off = 16; off; off >>= 1) {
                unsigned long long o = __shfl_down_sync(FULL, best, off);
                if (o < best) best = o;
            }
            if (lane == 0) {
                s_u[r + 1]   = dec_f((unsigned)(best >> 9));
                s_rowarg[r]  = (short)(best & 0x1FFu);
            }
        }
    }
    __syncthreads();
    if (tid == 0) {
        unsigned am = 0;
        for (int r = 0; r < MT; ++r) {
            int j = (int)s_rowarg[r];
            if (s_p[j] == 0) { s_p[j] = (short)(r + 1); am |= 1u << r; }
        }
        s_amask = am;
    }
    __syncthreads();

    // ---- speculative L2 prefetch of greedy-matched rows (hint only) ----
    {
        unsigned am = s_amask;
        for (int r = wrp; r < MT; r += 10) {
            if ((am >> r) & 1) {
                int idx = (int)s_rowarg[r] - 1;
                const char* base = (const char*)(il + ((size_t)(f * NP + idx)) * KID);
                if (lane < 16)
                    asm volatile("prefetch.global.L2 [%0];" :: "l"(base + lane * 128));
                if (lane == 16)
                    asm volatile("prefetch.global.L2 [%0];"
                                 :: "l"((const char*)(pb + (size_t)(f * NP + idx) * 4)));
            }
        }
    }

    // ---- phase 2b: Dijkstra only for contested rows (R8, proven) ----
    {
        const float FINF = 3.4e38f;
        const unsigned amask = s_amask;
        const bool owner = (tid < NP);       // owns column col = tid+1
        const int  col   = tid + 1;

        float v_j = 0.0f, minv_j = FINF;
        bool used_j = false;
        int parity = 0;

        for (int i = 1; i <= MT; ++i) {
            if ((amask >> (i - 1)) & 1) continue;   // greedy-assigned
            int i0 = i;       // carried row index
            int j0 = 0;       // predecessor column for way[]
            while (true) {
                float ui0 = s_u[i0];
                unsigned e = 0xFFFFFFFFu;
                if (owner && !used_j) {
                    float cur = s_cost[(i0 - 1) * NP + tid] - ui0 - v_j;
                    if (cur < minv_j) { minv_j = cur; s_way[col] = (short)j0; }
                    e = enc_f(minv_j);
                }
                // stage 1: HW warp argmin; lowest lane = smallest col
                unsigned m    = __reduce_min_sync(FULL, e);
                unsigned ball = __ballot_sync(FULL, e == m);
                if (lane == 0) {
                    s_wenc[parity][wrp] = m;
                    s_widx[parity][wrp] = wrp * 32 + (__ffs(ball) - 1) + 1;
                }
                __syncthreads();
                // stage 2: each warp redundantly reduces the 10 partials
                unsigned e2 = (lane < 10) ? s_wenc[parity][lane] : 0xFFFFFFFFu;
                unsigned c2 = (lane < 10) ? (unsigned)s_widx[parity][lane] : 0xFFFFFFFFu;
                unsigned m2 = __reduce_min_sync(FULL, e2);
                unsigned cc = (e2 == m2) ? c2 : 0xFFFFFFFFu;
                unsigned j1 = __reduce_min_sync(FULL, cc);
                float delta = dec_f(m2);
                parity ^= 1;

                int pj1 = (int)s_p[j1];
                if (owner) {
                    if (used_j) {
                        s_u[(int)s_p[col]] += delta;   // distinct tree rows
                        v_j -= delta;
                    } else {
                        minv_j -= delta;
                        if (col == (int)j1) used_j = true;
                    }
                }
                if (tid == NP) s_u[i] += delta;        // current row
                j0 = (int)j1;
                i0 = pj1;
                if (pj1 == 0) break;
            }
            __syncthreads();
            if (tid == 0) {
                int jj = j0;
                while (true) {
                    int jn = (int)s_way[jj];
                    short pv = (jn == 0) ? (short)i : s_p[jn];
                    s_p[jj] = pv;
                    if (jn == 0) break;
                    jj = jn;
                }
            }
            minv_j = FINF;
            used_j = false;
            __syncthreads();
        }
        if (owner) {
            int pc = (int)s_p[col];
            if (pc > 0) s_pidx[pc - 1] = col - 1;
        }
    }
    __syncthreads();

    // ---- phase 3: loss partials, software-pipelined (warp m, m+10, ...) ----
    {
        int m = wrp;                         // wrp < 10 <= MT, always valid
        int idx = s_pidx[m];
        float4 x[4];
        float  lt;
        float4 pbox;
        {
            const float4* row4 = (const float4*)(il + ((size_t)(f * NP + idx)) * KID);
            #pragma unroll
            for (int k = 0; k < 4; ++k) x[k] = row4[lane + 32 * k];
            lt   = il[((size_t)(f * NP + idx)) * KID + tids[f * MT + m]];
            pbox = ((const float4*)pb)[f * NP + idx];
        }
        while (true) {
            // prefetch next target's data before reducing current
            int mn = m + 10;
            float4 y[4];
            float  ltn = 0.0f;
            float4 pboxn = make_float4(0.f, 0.f, 0.f, 0.f);
            if (mn < MT) {
                int idxn = s_pidx[mn];
                const float4* r4 = (const float4*)(il + ((size_t)(f * NP + idxn)) * KID);
                #pragma unroll
                for (int k = 0; k < 4; ++k) y[k] = r4[lane + 32 * k];
                ltn   = il[((size_t)(f * NP + idxn)) * KID + tids[f * MT + mn]];
                pboxn = ((const float4*)pb)[f * NP + idxn];
            }
            // reduce current target (arithmetic order identical to R11)
            float mx = -INFINITY;
            #pragma unroll
            for (int k = 0; k < 4; ++k)
                mx = fmaxf(mx, fmaxf(fmaxf(x[k].x, x[k].y), fmaxf(x[k].z, x[k].w)));
            #pragma unroll
            for (int off = 16; off; off >>= 1)
                mx = fmaxf(mx, __shfl_xor_sync(FULL, mx, off));
            float se = 0.0f;
            #pragma unroll
            for (int k = 0; k < 4; ++k) {
                se += __expf(x[k].x - mx) + __expf(x[k].y - mx)
                    + __expf(x[k].z - mx) + __expf(x[k].w - mx);
            }
            #pragma unroll
            for (int off = 16; off; off >>= 1)
                se += __shfl_xor_sync(FULL, se, off);

            if (lane == 0) {
                s_nll[m] = (mx + __logf(se)) - lt;

                float cx = pbox.x, cy = pbox.y, w = pbox.z, h = pbox.w;
                float bcx = s_tb[m][0], bcy = s_tb[m][1], bw = s_tb[m][2], bh = s_tb[m][3];
                s_l1[m] = fabsf(cx - bcx) + fabsf(cy - bcy) + fabsf(w - bw) + fabsf(h - bh);

                float ax0 = cx - 0.5f * w, ay0 = cy - 0.5f * h;
                float ax1 = cx + 0.5f * w, ay1 = cy + 0.5f * h;
                float bx0 = bcx - 0.5f * bw, by0 = bcy - 0.5f * bh;
                float bx1 = bcx + 0.5f * bw, by1 = bcy + 0.5f * bh;
                float area1 = (ax1 - ax0) * (ay1 - ay0);
                float area2 = (bx1 - bx0) * (by1 - by0);
                float iw = fmaxf(fminf(ax1, bx1) - fmaxf(ax0, bx0), 0.0f);
                float ih = fmaxf(fminf(ay1, by1) - fmaxf(ay0, by0), 0.0f);
                float inter = iw * ih;
                float uni = area1 + area2 - inter;
                float iou = inter / uni;
                float cw = fmaxf(fmaxf(ax1, bx1) - fminf(ax0, bx0), 0.0f);
                float ch = fmaxf(fmaxf(ay1, by1) - fminf(ay0, by0), 0.0f);
                float ac = cw * ch;
                s_g[m] = iou - (ac - uni) / ac;
            }
            if (mn >= MT) break;
            m = mn;
            #pragma unroll
            for (int k = 0; k < 4; ++k) x[k] = y[k];
            lt = ltn;
            pbox = pboxn;
        }
    }
    __syncthreads();
    if (tid == 0) {
        double a = 0.0, b = 0.0, c = 0.0;
        #pragma unroll
        for (int k = 0; k < MT; ++k) {
            a += (double)s_l1[k]; b += (double)s_g[k]; c += (double)s_nll[k];
        }
        g_part[f * 3 + 0] = a;
        g_part[f * 3 + 1] = b;
        g_part[f * 3 + 2] = c;
        __threadfence();
        int prev = atomicAdd(&g_done, 1);
        s_last = (prev == FF - 1) ? 1 : 0;
    }
    __syncthreads();

    // ---- last block: deterministic final reduction ----
    if (s_last) {                       // block-uniform
        __threadfence();                // acquire for g_part reads
        double a = 0.0, b = 0.0, c = 0.0;
        if (tid < 128) {
            a = g_part[tid * 3 + 0];
            b = g_part[tid * 3 + 1];
            c = g_part[tid * 3 + 2];
        }
        #pragma unroll
        for (int off = 16; off; off >>= 1) {
            a += __shfl_down_sync(FULL, a, off);
            b += __shfl_down_sync(FULL, b, off);
            c += __shfl_down_sync(FULL, c, off);
        }
        if (wrp < 4 && lane == 0) { sa[wrp] = a; sb[wrp] = b; sc[wrp] = c; }
        __syncthreads();
        if (tid == 0) {
            double A  = sa[0] + sa[1] + sa[2] + sa[3];
            double B  = sb[0] + sb[1] + sb[2] + sb[3];
            double Cc = sc[0] + sc[1] + sc[2] + sc[3];
            double loss_l1   = A / (double)(FF * MT * 4);
            double loss_giou = 1.0 - B / (double)(FF * MT);
            double loss_id   = Cc / (double)(FF * MT);
            double loss = 5.0 * loss_l1 + 2.0 * loss_giou + 1.0 * loss_id;
            out[0] = (float)loss;
            out[1] = 0.0f;
            out[2] = (float)loss_l1;
            out[3] = (float)loss_giou;
            out[4] = (float)loss_id;
            g_done = 0;                 // reset for next graph replay
        }
    }
}

extern "C" void kernel_launch(void* const* d_in, const int* in_sizes, int n_in,
                              void* d_out, int out_size) {
    const float* pred_logits   = (const float*)d_in[0];   // [8,16,300,2]
    const float* pred_boxes    = (const float*)d_in[1];   // [8,16,300,4]
    const float* id_logits     = (const float*)d_in[2];   // [8,16,300,512]
    const int*   target_labels = (const int*)  d_in[3];   // [128,32]
    const float* target_boxes  = (const float*)d_in[4];   // [128,32,4]
    const int*   target_ids    = (const int*)  d_in[5];   // [128,32]
    float* out = (float*)d_out;

    fused_kernel<<<FF, NTH>>>(pred_logits, pred_boxes, id_logits,
                              target_labels, target_boxes, target_ids, out);
}

// round 14
// speedup vs baseline: 1.1489x; 1.1489x over previous
#include <cuda_runtime.h>
#include <math.h>
#include <stdint.h>

#define FF  128     // frames
#define NP  300     // predictions per frame
#define MT  32      // targets per frame
#define KID 512     // id classes
#define NTH 320     // threads per block (10 warps)

__device__ double g_part[FF * 3];   // per-frame partials: l1, giou, nll
__device__ int    g_done = 0;       // completion counter (self-resetting)

// order-preserving map float -> uint32 (total order, equality preserved)
__device__ __forceinline__ unsigned enc_f(float d) {
    int u = __float_as_int(d);
    return (unsigned)(u ^ ((u >> 31) | 0x80000000));
}
__device__ __forceinline__ float dec_f(unsigned e) {
    int u = (e & 0x80000000u) ? (int)(e ^ 0x80000000u) : ~(int)e;
    return __int_as_float(u);
}

// ============================================================
// Fused kernel, one block (320 threads) per frame:
// cost (shared, f32, exact IEEE division) -> row reduction +
// greedy pass 1 (v=0 dual-feasible warm start; column-based
// warm starts are dual-INFEASIBLE for rectangular assignment)
// -> Dijkstra for contested rows -> loss partials ->
// last-block final reduction.
// ============================================================
__global__ void __launch_bounds__(NTH, 1)
fused_kernel(const float* __restrict__ pl,
             const float* __restrict__ pb,
             const float* __restrict__ il,
             const int*   __restrict__ labels,
             const float* __restrict__ tbx,
             const int*   __restrict__ tids,
             float* __restrict__ out) {
    __shared__ float  s_cost[MT * NP];      // 38400 B [m][n]
    __shared__ float  s_u[MT + 2];
    __shared__ short  s_p[NP + 1];
    __shared__ short  s_way[NP + 1];
    __shared__ short  s_rowarg[MT];         // 1-based greedy argmin col per row
    __shared__ unsigned s_amask;            // greedy-assigned rows bitmask
    __shared__ unsigned s_wenc[2][10];
    __shared__ int      s_widx[2][10];
    __shared__ int    s_pidx[MT];
    __shared__ float  s_tb[MT][4];
    __shared__ int    s_lab[MT];
    __shared__ float  s_l1[MT], s_g[MT], s_nll[MT];
    __shared__ int    s_last;
    __shared__ double sa[4], sb[4], sc[4];

    const int f    = blockIdx.x;
    const int tid  = threadIdx.x;
    const int lane = tid & 31;
    const int wrp  = tid >> 5;
    const unsigned FULL = 0xFFFFFFFFu;

    // ---- stage targets + init ----
    if (tid < MT) {
        s_lab[tid] = labels[f * MT + tid];
        #pragma unroll
        for (int c = 0; c < 4; ++c) s_tb[tid][c] = tbx[(f * MT + tid) * 4 + c];
    }
    if (tid < MT + 2) s_u[tid] = 0.0f;
    if (tid <= NP) s_p[tid] = 0;
    __syncthreads();

    // ---- phase 1: cost matrix (column n = tid, loop over m), exact division ----
    if (tid < NP) {
        const int n = tid;
        float2 lg = ((const float2*)pl)[f * NP + n];
        float mx = fmaxf(lg.x, lg.y);
        float e0 = __expf(lg.x - mx), e1 = __expf(lg.y - mx);
        float inv = 1.0f / (e0 + e1);
        float p0 = e0 * inv, p1 = e1 * inv;
        float4 box = ((const float4*)pb)[f * NP + n];
        float cx = box.x, cy = box.y, w = box.z, h = box.w;
        float ax0 = cx - 0.5f * w, ay0 = cy - 0.5f * h;
        float ax1 = cx + 0.5f * w, ay1 = cy + 0.5f * h;
        float area1 = (ax1 - ax0) * (ay1 - ay0);
        #pragma unroll 4
        for (int m = 0; m < MT; ++m) {
            float bcx = s_tb[m][0], bcy = s_tb[m][1], bw = s_tb[m][2], bh = s_tb[m][3];
            float bx0 = bcx - 0.5f * bw, by0 = bcy - 0.5f * bh;
            float bx1 = bcx + 0.5f * bw, by1 = bcy + 0.5f * bh;
            float area2 = (bx1 - bx0) * (by1 - by0);
            float iw = fmaxf(fminf(ax1, bx1) - fmaxf(ax0, bx0), 0.0f);
            float ih = fmaxf(fminf(ay1, by1) - fmaxf(ay0, by0), 0.0f);
            float inter = iw * ih;
            float uni = area1 + area2 - inter;
            float iou = inter / uni;
            float cw = fmaxf(fmaxf(ax1, bx1) - fminf(ax0, bx0), 0.0f);
            float ch = fmaxf(fmaxf(ay1, by1) - fminf(ay0, by0), 0.0f);
            float ac = cw * ch;
            float giou = iou - (ac - uni) / ac;
            float l1c = fabsf(cx - bcx) + fabsf(cy - bcy) + fabsf(w - bw) + fabsf(h - bh);
            float prob = (s_lab[m] == 0) ? p0 : p1;
            s_cost[m * NP + n] = -2.0f * prob + 5.0f * l1c - 2.0f * giou;
        }
    }
    __syncthreads();

    // ---- phase 2a: row reduction + greedy assignment (R8 semantics,
    // cross-lane reduction via redux.sync; tie-break identical) ----
    {
        const unsigned long long UMAX = 0xFFFFFFFFFFFFFFFFULL;
        for (int r = wrp; r < MT; r += 10) {
            const float* crow = s_cost + r * NP;
            unsigned long long best = UMAX;      // (enc<<9)|col — lex order
            for (int j = lane; j < NP; j += 32) {
                unsigned long long key =
                    ((unsigned long long)enc_f(crow[j]) << 9) | (unsigned)(j + 1);
                if (key < best) best = key;
            }
            unsigned be = (unsigned)(best >> 9);
            unsigned bc = (unsigned)(best & 0x1FFu);
            unsigned m  = __reduce_min_sync(FULL, be);
            unsigned cc = (be == m) ? bc : 0xFFFFFFFFu;
            unsigned jm = __reduce_min_sync(FULL, cc);
            if (lane == 0) {
                s_u[r + 1]  = dec_f(m);
                s_rowarg[r] = (short)jm;
            }
        }
    }
    __syncthreads();
    if (tid == 0) {
        unsigned am = 0;
        for (int r = 0; r < MT; ++r) {
            int j = (int)s_rowarg[r];
            if (s_p[j] == 0) { s_p[j] = (short)(r + 1); am |= 1u << r; }
        }
        s_amask = am;
    }
    __syncthreads();

    // ---- phase 2b: Dijkstra only for contested rows (R8, proven) ----
    {
        const float FINF = 3.4e38f;
        const unsigned amask = s_amask;
        const bool owner = (tid < NP);       // owns column col = tid+1
        const int  col   = tid + 1;

        float v_j = 0.0f, minv_j = FINF;
        bool used_j = false;
        int parity = 0;

        for (int i = 1; i <= MT; ++i) {
            if ((amask >> (i - 1)) & 1) continue;   // greedy-assigned
            int i0 = i;       // carried row index
            int j0 = 0;       // predecessor column for way[]
            while (true) {
                float ui0 = s_u[i0];
                unsigned e = 0xFFFFFFFFu;
                if (owner && !used_j) {
                    float cur = s_cost[(i0 - 1) * NP + tid] - ui0 - v_j;
                    if (cur < minv_j) { minv_j = cur; s_way[col] = (short)j0; }
                    e = enc_f(minv_j);
                }
                // stage 1: HW warp argmin; lowest lane = smallest col
                unsigned m    = __reduce_min_sync(FULL, e);
                unsigned ball = __ballot_sync(FULL, e == m);
                if (lane == 0) {
                    s_wenc[parity][wrp] = m;
                    s_widx[parity][wrp] = wrp * 32 + (__ffs(ball) - 1) + 1;
                }
                __syncthreads();
                // stage 2: each warp redundantly reduces the 10 partials
                unsigned e2 = (lane < 10) ? s_wenc[parity][lane] : 0xFFFFFFFFu;
                unsigned c2 = (lane < 10) ? (unsigned)s_widx[parity][lane] : 0xFFFFFFFFu;
                unsigned m2 = __reduce_min_sync(FULL, e2);
                unsigned cc = (e2 == m2) ? c2 : 0xFFFFFFFFu;
                unsigned j1 = __reduce_min_sync(FULL, cc);
                float delta = dec_f(m2);
                parity ^= 1;

                int pj1 = (int)s_p[j1];
                if (owner) {
                    if (used_j) {
                        s_u[(int)s_p[col]] += delta;   // distinct tree rows
                        v_j -= delta;
                    } else {
                        minv_j -= delta;
                        if (col == (int)j1) used_j = true;
                    }
                }
                if (tid == NP) s_u[i] += delta;        // current row
                j0 = (int)j1;
                i0 = pj1;
                if (pj1 == 0) break;
            }
            __syncthreads();
            if (tid == 0) {
                int jj = j0;
                while (true) {
                    int jn = (int)s_way[jj];
                    short pv = (jn == 0) ? (short)i : s_p[jn];
                    s_p[jj] = pv;
                    if (jn == 0) break;
                    jj = jn;
                }
            }
            minv_j = FINF;
            used_j = false;
            __syncthreads();
        }
        if (owner) {
            int pc = (int)s_p[col];
            if (pc > 0) s_pidx[pc - 1] = col - 1;
        }
    }
    __syncthreads();

    // ---- phase 3: loss partials (warp handles m, m+10, m+20, ...) ----
    for (int m = wrp; m < MT; m += 10) {
        int idx = s_pidx[m];
        const float4* row4 = (const float4*)(il + ((size_t)(f * NP + idx)) * KID);
        float se = 0.0f;
        #pragma unroll
        for (int k = 0; k < 4; ++k) {
            float4 x = row4[lane + 32 * k];
            se += __expf(x.x) + __expf(x.y) + __expf(x.z) + __expf(x.w);
        }
        #pragma unroll
        for (int off = 16; off; off >>= 1) se += __shfl_xor_sync(FULL, se, off);

        if (lane == 0) {
            int t = tids[f * MT + m];
            float logit_t = il[((size_t)(f * NP + idx)) * KID + t];
            s_nll[m] = __logf(se) - logit_t;

            float4 box = ((const float4*)pb)[f * NP + idx];
            float cx = box.x, cy = box.y, w = box.z, h = box.w;
            float bcx = s_tb[m][0], bcy = s_tb[m][1], bw = s_tb[m][2], bh = s_tb[m][3];
            s_l1[m] = fabsf(cx - bcx) + fabsf(cy - bcy) + fabsf(w - bw) + fabsf(h - bh);

            float ax0 = cx - 0.5f * w, ay0 = cy - 0.5f * h;
            float ax1 = cx + 0.5f * w, ay1 = cy + 0.5f * h;
            float bx0 = bcx - 0.5f * bw, by0 = bcy - 0.5f * bh;
            float bx1 = bcx + 0.5f * bw, by1 = bcy + 0.5f * bh;
            float area1 = (ax1 - ax0) * (ay1 - ay0);
            float area2 = (bx1 - bx0) * (by1 - by0);
            float iw = fmaxf(fminf(ax1, bx1) - fmaxf(ax0, bx0), 0.0f);
            float ih = fmaxf(fminf(ay1, by1) - fmaxf(ay0, by0), 0.0f);
            float inter = iw * ih;
            float uni = area1 + area2 - inter;
            float iou = inter / uni;
            float cw = fmaxf(fmaxf(ax1, bx1) - fminf(ax0, bx0), 0.0f);
            float ch = fmaxf(fmaxf(ay1, by1) - fminf(ay0, by0), 0.0f);
            float ac = cw * ch;
            s_g[m] = iou - (ac - uni) / ac;
        }
    }
    __syncthreads();

    // ---- per-block partials: warp-0 deterministic f64 shuffle tree ----
    if (wrp == 0) {
        double a = (double)s_l1[lane];
        double b = (double)s_g[lane];
        double c = (double)s_nll[lane];
        #pragma unroll
        for (int off = 16; off; off >>= 1) {
            a += __shfl_xor_sync(FULL, a, off);
            b += __shfl_xor_sync(FULL, b, off);
            c += __shfl_xor_sync(FULL, c, off);
        }
        if (lane == 0) {
            g_part[f * 3 + 0] = a;
            g_part[f * 3 + 1] = b;
            g_part[f * 3 + 2] = c;
            __threadfence();
            int prev = atomicAdd(&g_done, 1);
            s_last = (prev == FF - 1) ? 1 : 0;
        }
    }
    __syncthreads();

    // ---- last block: deterministic final reduction ----
    if (s_last) {                       // block-uniform
        __threadfence();                // acquire for g_part reads
        double a = 0.0, b = 0.0, c = 0.0;
        if (tid < 128) {
            a = g_part[tid * 3 + 0];
            b = g_part[tid * 3 + 1];
            c = g_part[tid * 3 + 2];
        }
        #pragma unroll
        for (int off = 16; off; off >>= 1) {
            a += __shfl_down_sync(FULL, a, off);
            b += __shfl_down_sync(FULL, b, off);
            c += __shfl_down_sync(FULL, c, off);
        }
        if (wrp < 4 && lane == 0) { sa[wrp] = a; sb[wrp] = b; sc[wrp] = c; }
        __syncthreads();
        if (tid == 0) {
            double A  = sa[0] + sa[1] + sa[2] + sa[3];
            double B  = sb[0] + sb[1] + sb[2] + sb[3];
            double Cc = sc[0] + sc[1] + sc[2] + sc[3];
            double loss_l1   = A / (double)(FF * MT * 4);
            double loss_giou = 1.0 - B / (double)(FF * MT);
            double loss_id   = Cc / (double)(FF * MT);
            double loss = 5.0 * loss_l1 + 2.0 * loss_giou + 1.0 * loss_id;
            out[0] = (float)loss;
            out[1] = 0.0f;
            out[2] = (float)loss_l1;
            out[3] = (float)loss_giou;
            out[4] = (float)loss_id;
            g_done = 0;                 // reset for next graph replay
        }
    }
}

extern "C" void kernel_launch(void* const* d_in, const int* in_sizes, int n_in,
                              void* d_out, int out_size) {
    const float* pred_logits   = (const float*)d_in[0];   // [8,16,300,2]
    const float* pred_boxes    = (const float*)d_in[1];   // [8,16,300,4]
    const float* id_logits     = (const float*)d_in[2];   // [8,16,300,512]
    const int*   target_labels = (const int*)  d_in[3];   // [128,32]
    const float* target_boxes  = (const float*)d_in[4];   // [128,32,4]
    const int*   target_ids    = (const int*)  d_in[5];   // [128,32]
    float* out = (float*)d_out;

    fused_kernel<<<FF, NTH>>>(pred_logits, pred_boxes, id_logits,
                              target_labels, target_boxes, target_ids, out);
}

// round 15
// speedup vs baseline: 1.2236x; 1.0650x over previous
#include <cuda_runtime.h>
#include <math.h>
#include <stdint.h>

#define FF  128     // frames
#define NP  300     // predictions per frame
#define MT  32      // targets per frame
#define KID 512     // id classes
#define NTH 320     // threads per block (10 warps)

__device__ double g_part[FF * 3];   // per-frame partials: l1, giou, nll
__device__ int    g_done = 0;       // completion counter (self-resetting)

// order-preserving map float -> uint32 (total order, equality preserved)
__device__ __forceinline__ unsigned enc_f(float d) {
    int u = __float_as_int(d);
    return (unsigned)(u ^ ((u >> 31) | 0x80000000));
}
__device__ __forceinline__ float dec_f(unsigned e) {
    int u = (e & 0x80000000u) ? (int)(e ^ 0x80000000u) : ~(int)e;
    return __int_as_float(u);
}

// ============================================================
// Fused kernel, one block (320 threads) per frame:
// cost (shared, f32, exact IEEE division) -> row reduction +
// warp-parallel greedy pass 1 (match_any; v=0 dual-feasible)
// -> Dijkstra for contested rows -> loss partials (logit_t
// extracted from registers) -> last-block final reduction.
// ============================================================
__global__ void __launch_bounds__(NTH, 1)
fused_kernel(const float* __restrict__ pl,
             const float* __restrict__ pb,
             const float* __restrict__ il,
             const int*   __restrict__ labels,
             const float* __restrict__ tbx,
             const int*   __restrict__ tids,
             float* __restrict__ out) {
    __shared__ float  s_cost[MT * NP];      // 38400 B [m][n]
    __shared__ float  s_u[MT + 2];
    __shared__ short  s_p[NP + 1];
    __shared__ short  s_way[NP + 1];
    __shared__ short  s_rowarg[MT];         // 1-based greedy argmin col per row
    __shared__ unsigned s_amask;            // greedy-assigned rows bitmask
    __shared__ unsigned s_wenc[2][10];
    __shared__ int      s_widx[2][10];
    __shared__ int    s_pidx[MT];
    __shared__ float  s_tb[MT][4];
    __shared__ int    s_lab[MT];
    __shared__ float  s_l1[MT], s_g[MT], s_nll[MT];
    __shared__ int    s_last;
    __shared__ double sa[4], sb[4], sc[4];

    const int f    = blockIdx.x;
    const int tid  = threadIdx.x;
    const int lane = tid & 31;
    const int wrp  = tid >> 5;
    const unsigned FULL = 0xFFFFFFFFu;

    // ---- stage targets + init ----
    if (tid < MT) {
        s_lab[tid] = labels[f * MT + tid];
        #pragma unroll
        for (int c = 0; c < 4; ++c) s_tb[tid][c] = tbx[(f * MT + tid) * 4 + c];
    }
    if (tid < MT + 2) s_u[tid] = 0.0f;
    if (tid <= NP) s_p[tid] = 0;
    __syncthreads();

    // ---- phase 1: cost matrix (column n = tid, loop over m), exact division ----
    if (tid < NP) {
        const int n = tid;
        float2 lg = ((const float2*)pl)[f * NP + n];
        float mx = fmaxf(lg.x, lg.y);
        float e0 = __expf(lg.x - mx), e1 = __expf(lg.y - mx);
        float inv = 1.0f / (e0 + e1);
        float p0 = e0 * inv, p1 = e1 * inv;
        float4 box = ((const float4*)pb)[f * NP + n];
        float cx = box.x, cy = box.y, w = box.z, h = box.w;
        float ax0 = cx - 0.5f * w, ay0 = cy - 0.5f * h;
        float ax1 = cx + 0.5f * w, ay1 = cy + 0.5f * h;
        float area1 = (ax1 - ax0) * (ay1 - ay0);
        #pragma unroll 4
        for (int m = 0; m < MT; ++m) {
            float bcx = s_tb[m][0], bcy = s_tb[m][1], bw = s_tb[m][2], bh = s_tb[m][3];
            float bx0 = bcx - 0.5f * bw, by0 = bcy - 0.5f * bh;
            float bx1 = bcx + 0.5f * bw, by1 = bcy + 0.5f * bh;
            float area2 = (bx1 - bx0) * (by1 - by0);
            float iw = fmaxf(fminf(ax1, bx1) - fmaxf(ax0, bx0), 0.0f);
            float ih = fmaxf(fminf(ay1, by1) - fmaxf(ay0, by0), 0.0f);
            float inter = iw * ih;
            float uni = area1 + area2 - inter;
            float iou = inter / uni;
            float cw = fmaxf(fmaxf(ax1, bx1) - fminf(ax0, bx0), 0.0f);
            float ch = fmaxf(fmaxf(ay1, by1) - fminf(ay0, by0), 0.0f);
            float ac = cw * ch;
            float giou = iou - (ac - uni) / ac;
            float l1c = fabsf(cx - bcx) + fabsf(cy - bcy) + fabsf(w - bw) + fabsf(h - bh);
            float prob = (s_lab[m] == 0) ? p0 : p1;
            s_cost[m * NP + n] = -2.0f * prob + 5.0f * l1c - 2.0f * giou;
        }
    }
    __syncthreads();

    // ---- phase 2a: row reduction (redux.sync, R8 tie-break) ----
    {
        const unsigned long long UMAX = 0xFFFFFFFFFFFFFFFFULL;
        for (int r = wrp; r < MT; r += 10) {
            const float* crow = s_cost + r * NP;
            unsigned long long best = UMAX;      // (enc<<9)|col — lex order
            for (int j = lane; j < NP; j += 32) {
                unsigned long long key =
                    ((unsigned long long)enc_f(crow[j]) << 9) | (unsigned)(j + 1);
                if (key < best) best = key;
            }
            unsigned be = (unsigned)(best >> 9);
            unsigned bc = (unsigned)(best & 0x1FFu);
            unsigned m  = __reduce_min_sync(FULL, be);
            unsigned cc = (be == m) ? bc : 0xFFFFFFFFu;
            unsigned jm = __reduce_min_sync(FULL, cc);
            if (lane == 0) {
                s_u[r + 1]  = dec_f(m);
                s_rowarg[r] = (short)jm;
            }
        }
    }
    __syncthreads();

    // ---- greedy pass 1, warp-parallel via match_any (lowest row wins a
    // contested column == sequential first-come-first-served) ----
    if (wrp == 0) {
        int j = (int)s_rowarg[lane];            // lane == row r (MT == 32)
        unsigned peers = __match_any_sync(FULL, j);
        bool assigned = ((int)(__ffs(peers) - 1) == lane);
        if (assigned) s_p[j] = (short)(lane + 1);
        unsigned am = __ballot_sync(FULL, assigned);
        if (lane == 0) s_amask = am;
    }
    __syncthreads();

    // ---- phase 2b: Dijkstra only for contested rows (R8, proven) ----
    {
        const float FINF = 3.4e38f;
        const unsigned amask = s_amask;
        const bool owner = (tid < NP);       // owns column col = tid+1
        const int  col   = tid + 1;

        float v_j = 0.0f, minv_j = FINF;
        bool used_j = false;
        int parity = 0;

        for (int i = 1; i <= MT; ++i) {
            if ((amask >> (i - 1)) & 1) continue;   // greedy-assigned
            int i0 = i;       // carried row index
            int j0 = 0;       // predecessor column for way[]
            while (true) {
                float ui0 = s_u[i0];
                unsigned e = 0xFFFFFFFFu;
                if (owner && !used_j) {
                    float cur = s_cost[(i0 - 1) * NP + tid] - ui0 - v_j;
                    if (cur < minv_j) { minv_j = cur; s_way[col] = (short)j0; }
                    e = enc_f(minv_j);
                }
                // stage 1: HW warp argmin; lowest lane = smallest col
                unsigned m    = __reduce_min_sync(FULL, e);
                unsigned ball = __ballot_sync(FULL, e == m);
                if (lane == 0) {
                    s_wenc[parity][wrp] = m;
                    s_widx[parity][wrp] = wrp * 32 + (__ffs(ball) - 1) + 1;
                }
                __syncthreads();
                // stage 2: each warp redundantly reduces the 10 partials
                unsigned e2 = (lane < 10) ? s_wenc[parity][lane] : 0xFFFFFFFFu;
                unsigned c2 = (lane < 10) ? (unsigned)s_widx[parity][lane] : 0xFFFFFFFFu;
                unsigned m2 = __reduce_min_sync(FULL, e2);
                unsigned cc = (e2 == m2) ? c2 : 0xFFFFFFFFu;
                unsigned j1 = __reduce_min_sync(FULL, cc);
                float delta = dec_f(m2);
                parity ^= 1;

                int pj1 = (int)s_p[j1];
                if (owner) {
                    if (used_j) {
                        s_u[(int)s_p[col]] += delta;   // distinct tree rows
                        v_j -= delta;
                    } else {
                        minv_j -= delta;
                        if (col == (int)j1) used_j = true;
                    }
                }
                if (tid == NP) s_u[i] += delta;        // current row
                j0 = (int)j1;
                i0 = pj1;
                if (pj1 == 0) break;
            }
            __syncthreads();
            if (tid == 0) {
                int jj = j0;
                while (true) {
                    int jn = (int)s_way[jj];
                    short pv = (jn == 0) ? (short)i : s_p[jn];
                    s_p[jj] = pv;
                    if (jn == 0) break;
                    jj = jn;
                }
            }
            minv_j = FINF;
            used_j = false;
            __syncthreads();
        }
        if (owner) {
            int pc = (int)s_p[col];
            if (pc > 0) s_pidx[pc - 1] = col - 1;
        }
    }
    __syncthreads();

    // ---- phase 3: loss partials (warp handles m, m+10, m+20, ...) ----
    for (int m = wrp; m < MT; m += 10) {
        int idx = s_pidx[m];
        int t   = tids[f * MT + m];                   // early, uniform
        const float4* row4 = (const float4*)(il + ((size_t)(f * NP + idx)) * KID);
        float4 x[4];
        float se = 0.0f;
        #pragma unroll
        for (int k = 0; k < 4; ++k) x[k] = row4[lane + 32 * k];
        #pragma unroll
        for (int k = 0; k < 4; ++k)
            se += __expf(x[k].x) + __expf(x[k].y) + __expf(x[k].z) + __expf(x[k].w);
        #pragma unroll
        for (int off = 16; off; off >>= 1) se += __shfl_xor_sync(FULL, se, off);

        // extract logit_t from the lane that already holds it (same bits
        // as a reload: element t -> lane (t>>2)&31, word t>>7, comp t&3)
        int src_lane = (t >> 2) & 31;
        int kk = t >> 7;
        int c  = t & 3;
        float4 xv = x[kk];                            // kk uniform per warp
        float comp = (c == 0) ? xv.x : (c == 1) ? xv.y : (c == 2) ? xv.z : xv.w;
        float logit_t = __shfl_sync(FULL, comp, src_lane);

        if (lane == 0) {
            s_nll[m] = __logf(se) - logit_t;

            float4 box = ((const float4*)pb)[f * NP + idx];
            float cx = box.x, cy = box.y, w = box.z, h = box.w;
            float bcx = s_tb[m][0], bcy = s_tb[m][1], bw = s_tb[m][2], bh = s_tb[m][3];
            s_l1[m] = fabsf(cx - bcx) + fabsf(cy - bcy) + fabsf(w - bw) + fabsf(h - bh);

            float ax0 = cx - 0.5f * w, ay0 = cy - 0.5f * h;
            float ax1 = cx + 0.5f * w, ay1 = cy + 0.5f * h;
            float bx0 = bcx - 0.5f * bw, by0 = bcy - 0.5f * bh;
            float bx1 = bcx + 0.5f * bw, by1 = bcy + 0.5f * bh;
            float area1 = (ax1 - ax0) * (ay1 - ay0);
            float area2 = (bx1 - bx0) * (by1 - by0);
            float iw = fmaxf(fminf(ax1, bx1) - fmaxf(ax0, bx0), 0.0f);
            float ih = fmaxf(fminf(ay1, by1) - fmaxf(ay0, by0), 0.0f);
            float inter = iw * ih;
            float uni = area1 + area2 - inter;
            float iou = inter / uni;
            float cw = fmaxf(fmaxf(ax1, bx1) - fminf(ax0, bx0), 0.0f);
            float ch = fmaxf(fmaxf(ay1, by1) - fminf(ay0, by0), 0.0f);
            float ac = cw * ch;
            s_g[m] = iou - (ac - uni) / ac;
        }
    }
    __syncthreads();

    // ---- per-block partials: warp-0 deterministic f64 shuffle tree ----
    if (wrp == 0) {
        double a = (double)s_l1[lane];
        double b = (double)s_g[lane];
        double c = (double)s_nll[lane];
        #pragma unroll
        for (int off = 16; off; off >>= 1) {
            a += __shfl_xor_sync(FULL, a, off);
            b += __shfl_xor_sync(FULL, b, off);
            c += __shfl_xor_sync(FULL, c, off);
        }
        if (lane == 0) {
            g_part[f * 3 + 0] = a;
            g_part[f * 3 + 1] = b;
            g_part[f * 3 + 2] = c;
            __threadfence();
            int prev = atomicAdd(&g_done, 1);
            s_last = (prev == FF - 1) ? 1 : 0;
        }
    }
    __syncthreads();

    // ---- last block: deterministic final reduction ----
    if (s_last) {                       // block-uniform
        __threadfence();                // acquire for g_part reads
        double a = 0.0, b = 0.0, c = 0.0;
        if (tid < 128) {
            a = g_part[tid * 3 + 0];
            b = g_part[tid * 3 + 1];
            c = g_part[tid * 3 + 2];
        }
        #pragma unroll
        for (int off = 16; off; off >>= 1) {
            a += __shfl_down_sync(FULL, a, off);
            b += __shfl_down_sync(FULL, b, off);
            c += __shfl_down_sync(FULL, c, off);
        }
        if (wrp < 4 && lane == 0) { sa[wrp] = a; sb[wrp] = b; sc[wrp] = c; }
        __syncthreads();
        if (tid == 0) {
            double A  = sa[0] + sa[1] + sa[2] + sa[3];
            double B  = sb[0] + sb[1] + sb[2] + sb[3];
            double Cc = sc[0] + sc[1] + sc[2] + sc[3];
            double loss_l1   = A / (double)(FF * MT * 4);
            double loss_giou = 1.0 - B / (double)(FF * MT);
            double loss_id   = Cc / (double)(FF * MT);
            double loss = 5.0 * loss_l1 + 2.0 * loss_giou + 1.0 * loss_id;
            out[0] = (float)loss;
            out[1] = 0.0f;
            out[2] = (float)loss_l1;
            out[3] = (float)loss_giou;
            out[4] = (float)loss_id;
            g_done = 0;                 // reset for next graph replay
        }
    }
}

extern "C" void kernel_launch(void* const* d_in, const int* in_sizes, int n_in,
                              void* d_out, int out_size) {
    const float* pred_logits   = (const float*)d_in[0];   // [8,16,300,2]
    const float* pred_boxes    = (const float*)d_in[1];   // [8,16,300,4]
    const float* id_logits     = (const float*)d_in[2];   // [8,16,300,512]
    const int*   target_labels = (const int*)  d_in[3];   // [128,32]
    const float* target_boxes  = (const float*)d_in[4];   // [128,32,4]
    const int*   target_ids    = (const int*)  d_in[5];   // [128,32]
    float* out = (float*)d_out;

    fused_kernel<<<FF, NTH>>>(pred_logits, pred_boxes, id_logits,
                              target_labels, target_boxes, target_ids, out);
}

// round 16
// speedup vs baseline: 1.4198x; 1.1604x over previous
#include <cuda_runtime.h>
#include <math.h>
#include <stdint.h>

#define FF  128     // frames
#define NP  300     // predictions per frame
#define MT  32      // targets per frame
#define KID 512     // id classes
#define NTH 640     // threads per block (20 warps)

__device__ double g_part[FF * 3];   // per-frame partials: l1, giou, nll
__device__ int    g_done = 0;       // completion counter (self-resetting)

// order-preserving map float -> uint32 (total order, equality preserved)
__device__ __forceinline__ unsigned enc_f(float d) {
    int u = __float_as_int(d);
    return (unsigned)(u ^ ((u >> 31) | 0x80000000));
}
__device__ __forceinline__ float dec_f(unsigned e) {
    int u = (e & 0x80000000u) ? (int)(e ^ 0x80000000u) : ~(int)e;
    return __int_as_float(u);
}

// ============================================================
// Fused kernel, one block (640 threads) per frame:
// cost (shared, f32, exact IEEE division; 600 threads, half
// m-range each) -> row reduction + warp-parallel greedy pass 1
// (match_any; v=0 dual-feasible) -> Dijkstra for contested
// rows (columns owned by warps 0-9) -> loss partials (20
// warps, <=2 rounds) -> last-block final reduction.
// ============================================================
__global__ void __launch_bounds__(NTH, 1)
fused_kernel(const float* __restrict__ pl,
             const float* __restrict__ pb,
             const float* __restrict__ il,
             const int*   __restrict__ labels,
             const float* __restrict__ tbx,
             const int*   __restrict__ tids,
             float* __restrict__ out) {
    __shared__ float  s_cost[MT * NP];      // 38400 B [m][n]
    __shared__ float  s_u[MT + 2];
    __shared__ short  s_p[NP + 1];
    __shared__ short  s_way[NP + 1];
    __shared__ short  s_rowarg[MT];         // 1-based greedy argmin col per row
    __shared__ unsigned s_amask;            // greedy-assigned rows bitmask
    __shared__ unsigned s_wenc[2][10];
    __shared__ int      s_widx[2][10];
    __shared__ int    s_pidx[MT];
    __shared__ float  s_tb[MT][4];
    __shared__ int    s_lab[MT];
    __shared__ float  s_l1[MT], s_g[MT], s_nll[MT];
    __shared__ int    s_last;
    __shared__ double sa[4], sb[4], sc[4];

    const int f    = blockIdx.x;
    const int tid  = threadIdx.x;
    const int lane = tid & 31;
    const int wrp  = tid >> 5;
    const unsigned FULL = 0xFFFFFFFFu;

    // ---- stage targets + init ----
    if (tid < MT) {
        s_lab[tid] = labels[f * MT + tid];
        #pragma unroll
        for (int c = 0; c < 4; ++c) s_tb[tid][c] = tbx[(f * MT + tid) * 4 + c];
    }
    if (tid < MT + 2) s_u[tid] = 0.0f;
    if (tid <= NP) s_p[tid] = 0;
    __syncthreads();

    // ---- phase 1: cost matrix, 600 threads: n = tid mod 300, half m-range.
    // Per-(m,n) arithmetic identical to the 320-thread version (same bits).
    if (tid < 2 * NP) {
        const int n  = (tid < NP) ? tid : tid - NP;
        const int m0 = (tid < NP) ? 0 : (MT / 2);
        float2 lg = ((const float2*)pl)[f * NP + n];
        float mx = fmaxf(lg.x, lg.y);
        float e0 = __expf(lg.x - mx), e1 = __expf(lg.y - mx);
        float inv = 1.0f / (e0 + e1);
        float p0 = e0 * inv, p1 = e1 * inv;
        float4 box = ((const float4*)pb)[f * NP + n];
        float cx = box.x, cy = box.y, w = box.z, h = box.w;
        float ax0 = cx - 0.5f * w, ay0 = cy - 0.5f * h;
        float ax1 = cx + 0.5f * w, ay1 = cy + 0.5f * h;
        float area1 = (ax1 - ax0) * (ay1 - ay0);
        #pragma unroll 4
        for (int m = m0; m < m0 + MT / 2; ++m) {
            float bcx = s_tb[m][0], bcy = s_tb[m][1], bw = s_tb[m][2], bh = s_tb[m][3];
            float bx0 = bcx - 0.5f * bw, by0 = bcy - 0.5f * bh;
            float bx1 = bcx + 0.5f * bw, by1 = bcy + 0.5f * bh;
            float area2 = (bx1 - bx0) * (by1 - by0);
            float iw = fmaxf(fminf(ax1, bx1) - fmaxf(ax0, bx0), 0.0f);
            float ih = fmaxf(fminf(ay1, by1) - fmaxf(ay0, by0), 0.0f);
            float inter = iw * ih;
            float uni = area1 + area2 - inter;
            float iou = inter / uni;
            float cw = fmaxf(fmaxf(ax1, bx1) - fminf(ax0, bx0), 0.0f);
            float ch = fmaxf(fmaxf(ay1, by1) - fminf(ay0, by0), 0.0f);
            float ac = cw * ch;
            float giou = iou - (ac - uni) / ac;
            float l1c = fabsf(cx - bcx) + fabsf(cy - bcy) + fabsf(w - bw) + fabsf(h - bh);
            float prob = (s_lab[m] == 0) ? p0 : p1;
            s_cost[m * NP + n] = -2.0f * prob + 5.0f * l1c - 2.0f * giou;
        }
    }
    __syncthreads();

    // ---- phase 2a: row reduction (20 warps, <=2 rounds; R8 tie-break) ----
    {
        const unsigned long long UMAX = 0xFFFFFFFFFFFFFFFFULL;
        for (int r = wrp; r < MT; r += 20) {
            const float* crow = s_cost + r * NP;
            unsigned long long best = UMAX;      // (enc<<9)|col — lex order
            for (int j = lane; j < NP; j += 32) {
                unsigned long long key =
                    ((unsigned long long)enc_f(crow[j]) << 9) | (unsigned)(j + 1);
                if (key < best) best = key;
            }
            unsigned be = (unsigned)(best >> 9);
            unsigned bc = (unsigned)(best & 0x1FFu);
            unsigned m  = __reduce_min_sync(FULL, be);
            unsigned cc = (be == m) ? bc : 0xFFFFFFFFu;
            unsigned jm = __reduce_min_sync(FULL, cc);
            if (lane == 0) {
                s_u[r + 1]  = dec_f(m);
                s_rowarg[r] = (short)jm;
            }
        }
    }
    __syncthreads();

    // ---- greedy pass 1, warp-parallel via match_any (lowest row wins a
    // contested column == sequential first-come-first-served) ----
    if (wrp == 0) {
        int j = (int)s_rowarg[lane];            // lane == row r (MT == 32)
        unsigned peers = __match_any_sync(FULL, j);
        bool assigned = ((int)(__ffs(peers) - 1) == lane);
        if (assigned) s_p[j] = (short)(lane + 1);
        unsigned am = __ballot_sync(FULL, assigned);
        if (lane == 0) s_amask = am;
    }
    __syncthreads();

    // ---- phase 2b: Dijkstra only for contested rows (R8 semantics;
    // columns owned by warps 0-9, warps 10-19 barrier-participate) ----
    {
        const float FINF = 3.4e38f;
        const unsigned amask = s_amask;
        const bool owner = (tid < NP);       // owns column col = tid+1
        const int  col   = tid + 1;

        float v_j = 0.0f, minv_j = FINF;
        bool used_j = false;
        int parity = 0;

        for (int i = 1; i <= MT; ++i) {
            if ((amask >> (i - 1)) & 1) continue;   // greedy-assigned
            int i0 = i;       // carried row index
            int j0 = 0;       // predecessor column for way[]
            while (true) {
                float ui0 = s_u[i0];
                unsigned e = 0xFFFFFFFFu;
                if (owner && !used_j) {
                    float cur = s_cost[(i0 - 1) * NP + tid] - ui0 - v_j;
                    if (cur < minv_j) { minv_j = cur; s_way[col] = (short)j0; }
                    e = enc_f(minv_j);
                }
                // stage 1: HW warp argmin; lowest lane = smallest col
                unsigned m    = __reduce_min_sync(FULL, e);
                unsigned ball = __ballot_sync(FULL, e == m);
                if (wrp < 10 && lane == 0) {
                    s_wenc[parity][wrp] = m;
                    s_widx[parity][wrp] = wrp * 32 + (__ffs(ball) - 1) + 1;
                }
                __syncthreads();
                // stage 2: each warp redundantly reduces the 10 partials
                unsigned e2 = (lane < 10) ? s_wenc[parity][lane] : 0xFFFFFFFFu;
                unsigned c2 = (lane < 10) ? (unsigned)s_widx[parity][lane] : 0xFFFFFFFFu;
                unsigned m2 = __reduce_min_sync(FULL, e2);
                unsigned cc = (e2 == m2) ? c2 : 0xFFFFFFFFu;
                unsigned j1 = __reduce_min_sync(FULL, cc);
                float delta = dec_f(m2);
                parity ^= 1;

                int pj1 = (int)s_p[j1];
                if (owner) {
                    if (used_j) {
                        s_u[(int)s_p[col]] += delta;   // distinct tree rows
                        v_j -= delta;
                    } else {
                        minv_j -= delta;
                        if (col == (int)j1) used_j = true;
                    }
                }
                if (tid == NP) s_u[i] += delta;        // current row
                j0 = (int)j1;
                i0 = pj1;
                if (pj1 == 0) break;
            }
            __syncthreads();
            if (tid == 0) {
                int jj = j0;
                while (true) {
                    int jn = (int)s_way[jj];
                    short pv = (jn == 0) ? (short)i : s_p[jn];
                    s_p[jj] = pv;
                    if (jn == 0) break;
                    jj = jn;
                }
            }
            minv_j = FINF;
            used_j = false;
            __syncthreads();
        }
        if (owner) {
            int pc = (int)s_p[col];
            if (pc > 0) s_pidx[pc - 1] = col - 1;
        }
    }
    __syncthreads();

    // ---- phase 3: loss partials (20 warps: m, m+20 — <=2 rounds) ----
    for (int m = wrp; m < MT; m += 20) {
        int idx = s_pidx[m];
        int t   = tids[f * MT + m];                   // early, uniform
        const float4* row4 = (const float4*)(il + ((size_t)(f * NP + idx)) * KID);
        float4 x[4];
        float se = 0.0f;
        #pragma unroll
        for (int k = 0; k < 4; ++k) x[k] = row4[lane + 32 * k];
        #pragma unroll
        for (int k = 0; k < 4; ++k)
            se += __expf(x[k].x) + __expf(x[k].y) + __expf(x[k].z) + __expf(x[k].w);
        #pragma unroll
        for (int off = 16; off; off >>= 1) se += __shfl_xor_sync(FULL, se, off);

        // extract logit_t from the lane that already holds it (same bits
        // as a reload: element t -> lane (t>>2)&31, word t>>7, comp t&3)
        int src_lane = (t >> 2) & 31;
        int kk = t >> 7;
        int c  = t & 3;
        float4 xv = x[kk];                            // kk uniform per warp
        float comp = (c == 0) ? xv.x : (c == 1) ? xv.y : (c == 2) ? xv.z : xv.w;
        float logit_t = __shfl_sync(FULL, comp, src_lane);

        if (lane == 0) {
            s_nll[m] = __logf(se) - logit_t;

            float4 box = ((const float4*)pb)[f * NP + idx];
            float cx = box.x, cy = box.y, w = box.z, h = box.w;
            float bcx = s_tb[m][0], bcy = s_tb[m][1], bw = s_tb[m][2], bh = s_tb[m][3];
            s_l1[m] = fabsf(cx - bcx) + fabsf(cy - bcy) + fabsf(w - bw) + fabsf(h - bh);

            float ax0 = cx - 0.5f * w, ay0 = cy - 0.5f * h;
            float ax1 = cx + 0.5f * w, ay1 = cy + 0.5f * h;
            float bx0 = bcx - 0.5f * bw, by0 = bcy - 0.5f * bh;
            float bx1 = bcx + 0.5f * bw, by1 = bcy + 0.5f * bh;
            float area1 = (ax1 - ax0) * (ay1 - ay0);
            float area2 = (bx1 - bx0) * (by1 - by0);
            float iw = fmaxf(fminf(ax1, bx1) - fmaxf(ax0, bx0), 0.0f);
            float ih = fmaxf(fminf(ay1, by1) - fmaxf(ay0, by0), 0.0f);
            float inter = iw * ih;
            float uni = area1 + area2 - inter;
            float iou = inter / uni;
            float cw = fmaxf(fmaxf(ax1, bx1) - fminf(ax0, bx0), 0.0f);
            float ch = fmaxf(fmaxf(ay1, by1) - fminf(ay0, by0), 0.0f);
            float ac = cw * ch;
            s_g[m] = iou - (ac - uni) / ac;
        }
    }
    __syncthreads();

    // ---- per-block partials: warp-0 deterministic f64 shuffle tree ----
    if (wrp == 0) {
        double a = (double)s_l1[lane];
        double b = (double)s_g[lane];
        double c = (double)s_nll[lane];
        #pragma unroll
        for (int off = 16; off; off >>= 1) {
            a += __shfl_xor_sync(FULL, a, off);
            b += __shfl_xor_sync(FULL, b, off);
            c += __shfl_xor_sync(FULL, c, off);
        }
        if (lane == 0) {
            g_part[f * 3 + 0] = a;
            g_part[f * 3 + 1] = b;
            g_part[f * 3 + 2] = c;
            __threadfence();
            int prev = atomicAdd(&g_done, 1);
            s_last = (prev == FF - 1) ? 1 : 0;
        }
    }
    __syncthreads();

    // ---- last block: deterministic final reduction ----
    if (s_last) {                       // block-uniform
        __threadfence();                // acquire for g_part reads
        double a = 0.0, b = 0.0, c = 0.0;
        if (tid < 128) {
            a = g_part[tid * 3 + 0];
            b = g_part[tid * 3 + 1];
            c = g_part[tid * 3 + 2];
        }
        #pragma unroll
        for (int off = 16; off; off >>= 1) {
            a += __shfl_down_sync(FULL, a, off);
            b += __shfl_down_sync(FULL, b, off);
            c += __shfl_down_sync(FULL, c, off);
        }
        if (wrp < 4 && lane == 0) { sa[wrp] = a; sb[wrp] = b; sc[wrp] = c; }
        __syncthreads();
        if (tid == 0) {
            double A  = sa[0] + sa[1] + sa[2] + sa[3];
            double B  = sb[0] + sb[1] + sb[2] + sb[3];
            double Cc = sc[0] + sc[1] + sc[2] + sc[3];
            double loss_l1   = A / (double)(FF * MT * 4);
            double loss_giou = 1.0 - B / (double)(FF * MT);
            double loss_id   = Cc / (double)(FF * MT);
            double loss = 5.0 * loss_l1 + 2.0 * loss_giou + 1.0 * loss_id;
            out[0] = (float)loss;
            out[1] = 0.0f;
            out[2] = (float)loss_l1;
            out[3] = (float)loss_giou;
            out[4] = (float)loss_id;
            g_done = 0;                 // reset for next graph replay
        }
    }
}

extern "C" void kernel_launch(void* const* d_in, const int* in_sizes, int n_in,
                              void* d_out, int out_size) {
    const float* pred_logits   = (const float*)d_in[0];   // [8,16,300,2]
    const float* pred_boxes    = (const float*)d_in[1];   // [8,16,300,4]
    const float* id_logits     = (const float*)d_in[2];   // [8,16,300,512]
    const int*   target_labels = (const int*)  d_in[3];   // [128,32]
    const float* target_boxes  = (const float*)d_in[4];   // [128,32,4]
    const int*   target_ids    = (const int*)  d_in[5];   // [128,32]
    float* out = (float*)d_out;

    fused_kernel<<<FF, NTH>>>(pred_logits, pred_boxes, id_logits,
                              target_labels, target_boxes, target_ids, out);
}